// round 3
// baseline (speedup 1.0000x reference)
#include <cuda_runtime.h>

#define Nn 100000
#define Ee 1200000
#define Dd 64
#define NGIN 4
#define NPRED 5
#define NG 512

typedef unsigned long long ull;

__device__ __forceinline__ ull dup2(float x){
    ull r; asm("mov.b64 %0, {%1, %1};" : "=l"(r) : "f"(x)); return r;
}
__device__ __forceinline__ void fma2(ull &d, ull a, ull b){
    asm("fma.rn.f32x2 %0, %1, %2, %0;" : "+l"(d) : "l"(a), "l"(b));
}
__device__ __forceinline__ float2 u2f2(ull v){
    float2 f; asm("mov.b64 {%0, %1}, %2;" : "=f"(f.x), "=f"(f.y) : "l"(v)); return f;
}

// ---------------- scratch ----------------
__device__ float g_t[Nn*Dd];        // GEMM1 output
__device__ float g_u[Nn*Dd];        // GEMM2 output (pre-BN)
__device__ int   g_deg[Nn];
__device__ int   g_rowptr[Nn+1];
__device__ int   g_cursor[Nn];
__device__ int   g_col[Ee];
__device__ int   g_bsum[128];
__device__ int   g_bpre[128];
__device__ float g_stats[8*128];    // 8 slots: [0:64) sum, [64:128) sumsq
__device__ float g_pooled[NPRED*NG*Dd];

// ---------------- CSR build (+ fold all zeroing in) ----------------
__global__ void k_hist(const int* __restrict__ dst){
    int i = blockIdx.x*blockDim.x + threadIdx.x;
    if (i < Ee) atomicAdd(&g_deg[dst[i]], 1);
    if (i < NPRED*NG*Dd) g_pooled[i] = 0.f;
    if (i < 8*128) g_stats[i] = 0.f;
}

__global__ void k_scan1(){
    __shared__ int s[1024];
    int i = blockIdx.x*1024 + threadIdx.x;
    int v = 0;
    if (i < Nn){ v = g_deg[i]; g_deg[i] = 0; }   // self-clean for next replay
    s[threadIdx.x] = v;
    for (int off = 1; off < 1024; off <<= 1){
        __syncthreads();
        int x = (threadIdx.x >= off) ? s[threadIdx.x - off] : 0;
        __syncthreads();
        s[threadIdx.x] += x;
    }
    if (i < Nn) g_rowptr[i+1] = s[threadIdx.x];
    if (threadIdx.x == 1023) g_bsum[blockIdx.x] = s[1023];
}

__global__ void k_scan2(int nb){
    if (threadIdx.x == 0 && blockIdx.x == 0){
        int acc = 0;
        for (int b = 0; b < nb; b++){ int t = g_bsum[b]; g_bpre[b] = acc; acc += t; }
    }
}

__global__ void k_scan3(){
    int i = blockIdx.x*1024 + threadIdx.x;
    if (i < Nn){
        int v = g_rowptr[i+1] + g_bpre[blockIdx.x];
        g_rowptr[i+1] = v;
        if (i+1 < Nn) g_cursor[i+1] = v;
    }
    if (i == 0){ g_rowptr[0] = 0; g_cursor[0] = 0; }
}

__global__ void k_scatter(const int* __restrict__ src, const int* __restrict__ dst){
    int i = blockIdx.x*blockDim.x + threadIdx.x;
    if (i < Ee){
        int p = atomicAdd(&g_cursor[dst[i]], 1);
        g_col[p] = src[i];
    }
}

// ---------------- per-block BN coefficient computation (redundant, cheap) ----------------
__device__ __forceinline__ void bn_coeffs(const float* __restrict__ stats,
                                          const float* __restrict__ gamma,
                                          const float* __restrict__ beta,
                                          float* sA, float* sB, int tid)
{
    if (tid < 64){
        float m = stats[tid]    * (1.f/Nn);
        float v = stats[64+tid] * (1.f/Nn) - m*m;
        float a = gamma[tid] * rsqrtf(v + 1e-5f);
        sA[tid] = a;
        sB[tid] = beta[tid] - m*a;
    }
}

// ---------------- fused: [BN+relu ->] CSR-gather aggregation -> GEMM1 -> stats ----------------
// X_row(gr) = (1+eps)*f(h[gr]) + sum_{src in CSR(gr)} f(h[src]);  Y = X@W + bias
template<int MODE>
__global__ void __launch_bounds__(256) k_gemmA(const float* __restrict__ Hsrc,
                                               const float* __restrict__ eps, int layer,
                                               const float* __restrict__ W,
                                               const float* __restrict__ bias,
                                               float* __restrict__ Y,
                                               const float* __restrict__ statsIn,
                                               float* __restrict__ statsOut,
                                               const float* __restrict__ gamma,
                                               const float* __restrict__ beta)
{
    __shared__ float sXT[64][132];
    __shared__ float sW[64][64];
    __shared__ float sA[64], sB[64];
    __shared__ float sSum[64], sSsq[64];
    int tid = threadIdx.x;
    int rowBase = blockIdx.x * 128;
    if (tid < 64){ sSum[tid] = 0.f; sSsq[tid] = 0.f; }
    if (MODE) bn_coeffs(statsIn, gamma, beta, sA, sB, tid);

    // load W
    {
        const float4* W4 = (const float4*)W;
        float4* sW4 = (float4*)sW;
        #pragma unroll
        for (int i = 0; i < 4; i++) sW4[tid + i*256] = W4[tid + i*256];
    }
    __syncthreads();   // sA/sB ready for gather

    // gather phase: warp w handles rows w*16 .. w*16+15; lane owns cols (2*lane, 2*lane+1)
    {
        int wp   = tid >> 5;
        int lane = tid & 31;
        const float2* __restrict__ h2 = (const float2*)Hsrc;
        float Ax=1.f, Ay=1.f, Bx=0.f, By=0.f;
        if (MODE){
            Ax = sA[2*lane]; Ay = sA[2*lane+1];
            Bx = sB[2*lane]; By = sB[2*lane+1];
        }
        float epv = 1.f + eps[layer];
        for (int rr = 0; rr < 16; rr++){
            int r  = wp*16 + rr;
            int gr = rowBase + r;
            float ax = 0.f, ay = 0.f;
            if (gr < Nn){
                float2 s = h2[gr*32 + lane];
                float sx = s.x, sy = s.y;
                if (MODE){ sx = fmaxf(fmaf(sx,Ax,Bx),0.f); sy = fmaxf(fmaf(sy,Ay,By),0.f); }
                ax = sx * epv; ay = sy * epv;
                int e = g_rowptr[gr], end = g_rowptr[gr+1];
                for (; e + 4 <= end; e += 4){
                    int s0 = g_col[e], s1 = g_col[e+1], s2 = g_col[e+2], s3 = g_col[e+3];
                    float2 v0 = h2[s0*32+lane], v1 = h2[s1*32+lane];
                    float2 v2 = h2[s2*32+lane], v3 = h2[s3*32+lane];
                    if (MODE){
                        v0.x = fmaxf(fmaf(v0.x,Ax,Bx),0.f); v0.y = fmaxf(fmaf(v0.y,Ay,By),0.f);
                        v1.x = fmaxf(fmaf(v1.x,Ax,Bx),0.f); v1.y = fmaxf(fmaf(v1.y,Ay,By),0.f);
                        v2.x = fmaxf(fmaf(v2.x,Ax,Bx),0.f); v2.y = fmaxf(fmaf(v2.y,Ay,By),0.f);
                        v3.x = fmaxf(fmaf(v3.x,Ax,Bx),0.f); v3.y = fmaxf(fmaf(v3.y,Ay,By),0.f);
                    }
                    ax += (v0.x + v1.x) + (v2.x + v3.x);
                    ay += (v0.y + v1.y) + (v2.y + v3.y);
                }
                for (; e < end; e++){
                    int sI = g_col[e];
                    float2 v = h2[sI*32+lane];
                    if (MODE){
                        v.x = fmaxf(fmaf(v.x,Ax,Bx),0.f);
                        v.y = fmaxf(fmaf(v.y,Ay,By),0.f);
                    }
                    ax += v.x; ay += v.y;
                }
            }
            sXT[2*lane  ][r] = ax;
            sXT[2*lane+1][r] = ay;
        }
    }
    __syncthreads();

    // GEMM phase (FFMA2)
    int tr = tid >> 4;
    int tc = tid & 15;
    ull acc[4][4];
    #pragma unroll
    for (int i = 0; i < 4; i++)
        #pragma unroll
        for (int j = 0; j < 4; j++) acc[i][j] = 0ULL;

    #pragma unroll 16
    for (int k = 0; k < 64; k++){
        ulonglong2 a01 = *(const ulonglong2*)&sXT[k][tr*8];
        ulonglong2 a23 = *(const ulonglong2*)&sXT[k][tr*8 + 4];
        float4 wv = *(const float4*)&sW[k][tc*4];
        ull w0 = dup2(wv.x), w1 = dup2(wv.y), w2 = dup2(wv.z), w3 = dup2(wv.w);
        fma2(acc[0][0], a01.x, w0); fma2(acc[0][1], a01.x, w1);
        fma2(acc[0][2], a01.x, w2); fma2(acc[0][3], a01.x, w3);
        fma2(acc[1][0], a01.y, w0); fma2(acc[1][1], a01.y, w1);
        fma2(acc[1][2], a01.y, w2); fma2(acc[1][3], a01.y, w3);
        fma2(acc[2][0], a23.x, w0); fma2(acc[2][1], a23.x, w1);
        fma2(acc[2][2], a23.x, w2); fma2(acc[2][3], a23.x, w3);
        fma2(acc[3][0], a23.y, w0); fma2(acc[3][1], a23.y, w1);
        fma2(acc[3][2], a23.y, w2); fma2(acc[3][3], a23.y, w3);
    }

    float4 bi = ((const float4*)bias)[tc];
    float ls[4]  = {0.f,0.f,0.f,0.f};
    float lss[4] = {0.f,0.f,0.f,0.f};
    #pragma unroll
    for (int rp = 0; rp < 4; rp++){
        float2 c0 = u2f2(acc[rp][0]);
        float2 c1 = u2f2(acc[rp][1]);
        float2 c2 = u2f2(acc[rp][2]);
        float2 c3 = u2f2(acc[rp][3]);
        int gr = rowBase + tr*8 + rp*2;
        if (gr < Nn){
            float4 o;
            o.x = c0.x + bi.x; o.y = c1.x + bi.y; o.z = c2.x + bi.z; o.w = c3.x + bi.w;
            *(float4*)&Y[gr*64 + tc*4] = o;
            ls[0] += o.x; ls[1] += o.y; ls[2] += o.z; ls[3] += o.w;
            lss[0] += o.x*o.x; lss[1] += o.y*o.y; lss[2] += o.z*o.z; lss[3] += o.w*o.w;
        }
        if (gr + 1 < Nn){
            float4 o;
            o.x = c0.y + bi.x; o.y = c1.y + bi.y; o.z = c2.y + bi.z; o.w = c3.y + bi.w;
            *(float4*)&Y[(gr+1)*64 + tc*4] = o;
            ls[0] += o.x; ls[1] += o.y; ls[2] += o.z; ls[3] += o.w;
            lss[0] += o.x*o.x; lss[1] += o.y*o.y; lss[2] += o.z*o.z; lss[3] += o.w*o.w;
        }
    }
    #pragma unroll
    for (int c = 0; c < 4; c++){
        ls[c]  += __shfl_xor_sync(0xffffffffu, ls[c],  16);
        lss[c] += __shfl_xor_sync(0xffffffffu, lss[c], 16);
    }
    if ((tid & 31) < 16){
        #pragma unroll
        for (int c = 0; c < 4; c++){
            atomicAdd(&sSum[tc*4+c], ls[c]);
            atomicAdd(&sSsq[tc*4+c], lss[c]);
        }
    }
    __syncthreads();
    if (tid < 64){
        atomicAdd(&statsOut[tid],    sSum[tid]);
        atomicAdd(&statsOut[64+tid], sSsq[tid]);
    }
}

// ---------------- GEMM2: BN+relu on input (coeffs from slot) -> GEMM -> stats ----------------
__global__ void __launch_bounds__(256) k_gemmB(const float* __restrict__ X,
                                               const float* __restrict__ W,
                                               const float* __restrict__ bias,
                                               float* __restrict__ Y,
                                               const float* __restrict__ statsIn,
                                               float* __restrict__ statsOut,
                                               const float* __restrict__ gamma,
                                               const float* __restrict__ beta)
{
    __shared__ float sXT[64][132];
    __shared__ float sW[64][64];
    __shared__ float sA[64], sB[64];
    __shared__ float sSum[64], sSsq[64];
    int tid = threadIdx.x;
    int rowBase = blockIdx.x * 128;
    if (tid < 64){ sSum[tid] = 0.f; sSsq[tid] = 0.f; }
    bn_coeffs(statsIn, gamma, beta, sA, sB, tid);

    {
        const float4* W4 = (const float4*)W;
        float4* sW4 = (float4*)sW;
        #pragma unroll
        for (int i = 0; i < 4; i++) sW4[tid + i*256] = W4[tid + i*256];
    }
    __syncthreads();   // sA/sB ready

    #pragma unroll
    for (int k = 0; k < 8; k++){
        int l  = tid + k*256;
        int r  = l >> 4;
        int c4 = l & 15;
        int gr = rowBase + r;
        float4 x = make_float4(0.f,0.f,0.f,0.f);
        if (gr < Nn){
            x = ((const float4*)X)[gr*16 + c4];
            float4 A = ((const float4*)sA)[c4];
            float4 B = ((const float4*)sB)[c4];
            x.x = fmaxf(fmaf(x.x,A.x,B.x),0.f);
            x.y = fmaxf(fmaf(x.y,A.y,B.y),0.f);
            x.z = fmaxf(fmaf(x.z,A.z,B.z),0.f);
            x.w = fmaxf(fmaf(x.w,A.w,B.w),0.f);
        }
        int c = c4*4;
        sXT[c+0][r] = x.x; sXT[c+1][r] = x.y; sXT[c+2][r] = x.z; sXT[c+3][r] = x.w;
    }
    __syncthreads();

    int tr = tid >> 4;
    int tc = tid & 15;
    ull acc[4][4];
    #pragma unroll
    for (int i = 0; i < 4; i++)
        #pragma unroll
        for (int j = 0; j < 4; j++) acc[i][j] = 0ULL;

    #pragma unroll 16
    for (int k = 0; k < 64; k++){
        ulonglong2 a01 = *(const ulonglong2*)&sXT[k][tr*8];
        ulonglong2 a23 = *(const ulonglong2*)&sXT[k][tr*8 + 4];
        float4 wv = *(const float4*)&sW[k][tc*4];
        ull w0 = dup2(wv.x), w1 = dup2(wv.y), w2 = dup2(wv.z), w3 = dup2(wv.w);
        fma2(acc[0][0], a01.x, w0); fma2(acc[0][1], a01.x, w1);
        fma2(acc[0][2], a01.x, w2); fma2(acc[0][3], a01.x, w3);
        fma2(acc[1][0], a01.y, w0); fma2(acc[1][1], a01.y, w1);
        fma2(acc[1][2], a01.y, w2); fma2(acc[1][3], a01.y, w3);
        fma2(acc[2][0], a23.x, w0); fma2(acc[2][1], a23.x, w1);
        fma2(acc[2][2], a23.x, w2); fma2(acc[2][3], a23.x, w3);
        fma2(acc[3][0], a23.y, w0); fma2(acc[3][1], a23.y, w1);
        fma2(acc[3][2], a23.y, w2); fma2(acc[3][3], a23.y, w3);
    }

    float4 bi = ((const float4*)bias)[tc];
    float ls[4]  = {0.f,0.f,0.f,0.f};
    float lss[4] = {0.f,0.f,0.f,0.f};
    #pragma unroll
    for (int rp = 0; rp < 4; rp++){
        float2 c0 = u2f2(acc[rp][0]);
        float2 c1 = u2f2(acc[rp][1]);
        float2 c2 = u2f2(acc[rp][2]);
        float2 c3 = u2f2(acc[rp][3]);
        int gr = rowBase + tr*8 + rp*2;
        if (gr < Nn){
            float4 o;
            o.x = c0.x + bi.x; o.y = c1.x + bi.y; o.z = c2.x + bi.z; o.w = c3.x + bi.w;
            *(float4*)&Y[gr*64 + tc*4] = o;
            ls[0] += o.x; ls[1] += o.y; ls[2] += o.z; ls[3] += o.w;
            lss[0] += o.x*o.x; lss[1] += o.y*o.y; lss[2] += o.z*o.z; lss[3] += o.w*o.w;
        }
        if (gr + 1 < Nn){
            float4 o;
            o.x = c0.y + bi.x; o.y = c1.y + bi.y; o.z = c2.y + bi.z; o.w = c3.y + bi.w;
            *(float4*)&Y[(gr+1)*64 + tc*4] = o;
            ls[0] += o.x; ls[1] += o.y; ls[2] += o.z; ls[3] += o.w;
            lss[0] += o.x*o.x; lss[1] += o.y*o.y; lss[2] += o.z*o.z; lss[3] += o.w*o.w;
        }
    }
    #pragma unroll
    for (int c = 0; c < 4; c++){
        ls[c]  += __shfl_xor_sync(0xffffffffu, ls[c],  16);
        lss[c] += __shfl_xor_sync(0xffffffffu, lss[c], 16);
    }
    if ((tid & 31) < 16){
        #pragma unroll
        for (int c = 0; c < 4; c++){
            atomicAdd(&sSum[tc*4+c], ls[c]);
            atomicAdd(&sSsq[tc*4+c], lss[c]);
        }
    }
    __syncthreads();
    if (tid < 64){
        atomicAdd(&statsOut[tid],    sSum[tid]);
        atomicAdd(&statsOut[64+tid], sSsq[tid]);
    }
}

// ---------------- pooling (BN+relu fused, coeffs per block), sorted run-length ----------------
template<int MODE>
__global__ void k_pool(const float* __restrict__ U, const int* __restrict__ gid,
                       float* __restrict__ pooled,
                       const float* __restrict__ statsIn,
                       const float* __restrict__ gamma,
                       const float* __restrict__ beta)
{
    __shared__ float sA[64], sB[64];
    int tid = threadIdx.x;
    if (MODE){
        bn_coeffs(statsIn, gamma, beta, sA, sB, tid);
        __syncthreads();
    }
    int col  = tid & 63;
    int rl   = tid >> 6;
    int base = blockIdx.x * 128 + rl*32;
    float a = 1.f, b = 0.f;
    if (MODE){ a = sA[col]; b = sB[col]; }
    float acc = 0.f; int cur = -1;
    for (int j = 0; j < 32; j++){
        int r = base + j;
        if (r >= Nn) break;
        float x = U[r*64 + col];
        if (MODE) x = fmaxf(fmaf(x, a, b), 0.f);
        int g = gid[r];
        if (g != cur){
            if (cur >= 0) atomicAdd(&pooled[cur*64 + col], acc);
            cur = g; acc = x;
        } else {
            acc += x;
        }
    }
    if (cur >= 0) atomicAdd(&pooled[cur*64 + col], acc);
}

// ---------------- score = sum_i pooled_i @ Wp_i + bp_i ----------------
__global__ void k_score(const float* __restrict__ Wp, const float* __restrict__ bp,
                        float* __restrict__ out)
{
    int t = blockIdx.x*blockDim.x + threadIdx.x;
    if (t >= NG*16) return;
    int g = t >> 4, o = t & 15;
    float acc = 0.f;
    #pragma unroll
    for (int i = 0; i < NPRED; i++){
        const float* __restrict__ P  = &g_pooled[(i*NG + g)*64];
        const float* __restrict__ Wr = Wp + i*64*16 + o;
        float s = 0.f;
        #pragma unroll 16
        for (int k = 0; k < 64; k++) s = fmaf(P[k], Wr[k*16], s);
        acc += s + bp[i*16 + o];
    }
    out[t] = acc;
}

// ---------------- launch ----------------
extern "C" void kernel_launch(void* const* d_in, const int* in_sizes, int n_in,
                              void* d_out, int out_size)
{
    const float* h    = (const float*)d_in[0];
    const int*   esrc = (const int*)  d_in[1];
    const int*   edst = (const int*)  d_in[2];
    const int*   gid  = (const int*)  d_in[3];
    const float* eps  = (const float*)d_in[4];
    const float* W1   = (const float*)d_in[5];
    const float* b1   = (const float*)d_in[6];
    const float* g1   = (const float*)d_in[7];
    const float* be1  = (const float*)d_in[8];
    const float* W2   = (const float*)d_in[9];
    const float* b2   = (const float*)d_in[10];
    const float* g2   = (const float*)d_in[11];
    const float* be2  = (const float*)d_in[12];
    const float* Wp   = (const float*)d_in[13];
    const float* bp   = (const float*)d_in[14];
    float* out = (float*)d_out;

    void *p_pooled, *p_t, *p_u, *p_stats;
    cudaGetSymbolAddress(&p_pooled, g_pooled);
    cudaGetSymbolAddress(&p_t,      g_t);
    cudaGetSymbolAddress(&p_u,      g_u);
    cudaGetSymbolAddress(&p_stats,  g_stats);
    float* stats = (float*)p_stats;

    // CSR by destination (self-cleaning counters; zeroes pooled+stats too)
    k_hist<<<(Ee+255)/256, 256>>>(edst);
    int nb = (Nn + 1023)/1024;
    k_scan1<<<nb, 1024>>>();
    k_scan2<<<1, 32>>>(nb);
    k_scan3<<<nb, 1024>>>();
    k_scatter<<<(Ee+255)/256, 256>>>(esrc, edst);

    int poolB = (Nn + 127)/128;
    int gemmB = (Nn + 127)/128;

    // pooled[0] = segment_sum of raw input h
    k_pool<0><<<poolB, 256>>>(h, gid, (float*)p_pooled, nullptr, nullptr, nullptr);

    for (int i = 0; i < NGIN; i++){
        float* s1 = stats + (2*i)*128;      // BN1 stats (from gemmA output)
        float* s2 = stats + (2*i+1)*128;    // BN2 stats (from gemmB output)
        // BN coeffs for gather input (layer i>0): slot 2(i-1)+1 with g2/be2 of layer i-1
        const float* sIn = (i > 0) ? stats + (2*(i-1)+1)*128 : nullptr;
        const float* gIn = (i > 0) ? g2 + (i-1)*64 : nullptr;
        const float* bIn = (i > 0) ? be2 + (i-1)*64 : nullptr;

        if (i == 0)
            k_gemmA<0><<<gemmB, 256>>>(h, eps, i, W1 + i*4096, b1 + i*64,
                                       (float*)p_t, nullptr, s1, nullptr, nullptr);
        else
            k_gemmA<1><<<gemmB, 256>>>((const float*)p_u, eps, i, W1 + i*4096, b1 + i*64,
                                       (float*)p_t, sIn, s1, gIn, bIn);

        k_gemmB<<<gemmB, 256>>>((const float*)p_t, W2 + i*4096, b2 + i*64,
                                (float*)p_u, s1, s2, g1 + i*64, be1 + i*64);

        k_pool<1><<<poolB, 256>>>((const float*)p_u, gid,
                                  (float*)p_pooled + (size_t)(i+1)*NG*Dd,
                                  s2, g2 + i*64, be2 + i*64);
    }

    k_score<<<(NG*16 + 255)/256, 256>>>(Wp, bp, out);
}

// round 4
// speedup vs baseline: 1.1082x; 1.1082x over previous
#include <cuda_runtime.h>

#define Nn 100000
#define Ee 1200000
#define Dd 64
#define NGIN 4
#define NPRED 5
#define NG 512

typedef unsigned long long ull;

__device__ __forceinline__ ull dup2(float x){
    ull r; asm("mov.b64 %0, {%1, %1};" : "=l"(r) : "f"(x)); return r;
}
__device__ __forceinline__ void fma2(ull &d, ull a, ull b){
    asm("fma.rn.f32x2 %0, %1, %2, %0;" : "+l"(d) : "l"(a), "l"(b));
}
__device__ __forceinline__ float2 u2f2(ull v){
    float2 f; asm("mov.b64 {%0, %1}, %2;" : "=f"(f.x), "=f"(f.y) : "l"(v)); return f;
}

// ---------------- scratch ----------------
__device__ float g_pre[Nn*Dd];      // aggregation output
__device__ float g_t[Nn*Dd];        // GEMM1 output
__device__ float g_u[Nn*Dd];        // GEMM2 output (pre-BN)
__device__ int   g_deg[Nn];
__device__ int   g_rowptr[Nn+1];
__device__ int   g_cursor[Nn];
__device__ int   g_col[Ee];
__device__ int   g_bsum[128];
__device__ int   g_bpre[128];
__device__ float g_stats[8*128];    // 8 slots: [0:64) sum, [64:128) sumsq
__device__ float g_pooled[NPRED*NG*Dd];

// ---------------- CSR build (+ fold all zeroing in) ----------------
__global__ void k_hist(const int* __restrict__ dst){
    int i = blockIdx.x*blockDim.x + threadIdx.x;
    if (i < Ee) atomicAdd(&g_deg[dst[i]], 1);
    if (i < NPRED*NG*Dd) g_pooled[i] = 0.f;
    if (i < 8*128) g_stats[i] = 0.f;
}

__global__ void k_scan1(){
    __shared__ int s[1024];
    int i = blockIdx.x*1024 + threadIdx.x;
    int v = 0;
    if (i < Nn){ v = g_deg[i]; g_deg[i] = 0; }   // self-clean for next replay
    s[threadIdx.x] = v;
    for (int off = 1; off < 1024; off <<= 1){
        __syncthreads();
        int x = (threadIdx.x >= off) ? s[threadIdx.x - off] : 0;
        __syncthreads();
        s[threadIdx.x] += x;
    }
    if (i < Nn) g_rowptr[i+1] = s[threadIdx.x];
    if (threadIdx.x == 1023) g_bsum[blockIdx.x] = s[1023];
}

__global__ void k_scan2(int nb){
    if (threadIdx.x == 0 && blockIdx.x == 0){
        int acc = 0;
        for (int b = 0; b < nb; b++){ int t = g_bsum[b]; g_bpre[b] = acc; acc += t; }
    }
}

__global__ void k_scan3(){
    int i = blockIdx.x*1024 + threadIdx.x;
    if (i < Nn){
        int v = g_rowptr[i+1] + g_bpre[blockIdx.x];
        g_rowptr[i+1] = v;
        if (i+1 < Nn) g_cursor[i+1] = v;
    }
    if (i == 0){ g_rowptr[0] = 0; g_cursor[0] = 0; }
}

__global__ void k_scatter(const int* __restrict__ src, const int* __restrict__ dst){
    int i = blockIdx.x*blockDim.x + threadIdx.x;
    if (i < Ee){
        int p = atomicAdd(&g_cursor[dst[i]], 1);
        g_col[p] = src[i];
    }
}

// ---------------- per-block BN coefficient computation (redundant, cheap) ----------------
__device__ __forceinline__ void bn_coeffs(const float* __restrict__ stats,
                                          const float* __restrict__ gamma,
                                          const float* __restrict__ beta,
                                          float* sA, float* sB, int tid)
{
    if (tid < 64){
        float m = stats[tid]    * (1.f/Nn);
        float v = stats[64+tid] * (1.f/Nn) - m*m;
        float a = gamma[tid] * rsqrtf(v + 1e-5f);
        sA[tid] = a;
        sB[tid] = beta[tid] - m*a;
    }
}

// ---------------- aggregation (warp per node) with fused BN+relu on the source
// AND fused sum-pooling of the BN'd self value (= hidden_rep[layer]) ----------------
// pre = (1+eps)*f(h) + sum_{src->node} f(h[src]);  pooled[gid] += f(h[node])
template<int MODE>
__global__ void __launch_bounds__(256) k_agg(const float* __restrict__ hin,
                                             const float* __restrict__ eps, int layer,
                                             const int* __restrict__ gid,
                                             float* __restrict__ pooled,
                                             const float* __restrict__ statsIn,
                                             const float* __restrict__ gamma,
                                             const float* __restrict__ beta)
{
    __shared__ float sA[64], sB[64];
    __shared__ float sPool[8][64];
    __shared__ int   sGid[8];
    int tid  = threadIdx.x;
    int wp   = tid >> 5;
    int lane = tid & 31;
    int w    = blockIdx.x*8 + wp;            // node; Nn % 8 == 0 -> always valid

    if (MODE){
        bn_coeffs(statsIn, gamma, beta, sA, sB, tid);
        __syncthreads();
    }

    const float2* __restrict__ h2 = (const float2*)hin;
    float Ax=1.f, Ay=1.f, Bx=0.f, By=0.f;
    if (MODE){
        Ax = sA[2*lane]; Ay = sA[2*lane+1];
        Bx = sB[2*lane]; By = sB[2*lane+1];
    }
    float epv = 1.f + eps[layer];

    float2 s = h2[w*32 + lane];
    float fx = s.x, fy = s.y;
    if (MODE){ fx = fmaxf(fmaf(fx,Ax,Bx),0.f); fy = fmaxf(fmaf(fy,Ay,By),0.f); }
    // stage pooling contribution (pre-eps value = hidden_rep[layer][node])
    sPool[wp][2*lane]   = fx;
    sPool[wp][2*lane+1] = fy;
    if (lane == 0) sGid[wp] = gid[w];

    float ax = fx * epv, ay = fy * epv;
    int e = g_rowptr[w], end = g_rowptr[w+1];
    for (; e + 4 <= end; e += 4){
        int s0 = g_col[e], s1 = g_col[e+1], s2 = g_col[e+2], s3 = g_col[e+3];
        float2 v0 = h2[s0*32+lane], v1 = h2[s1*32+lane];
        float2 v2 = h2[s2*32+lane], v3 = h2[s3*32+lane];
        if (MODE){
            v0.x = fmaxf(fmaf(v0.x,Ax,Bx),0.f); v0.y = fmaxf(fmaf(v0.y,Ay,By),0.f);
            v1.x = fmaxf(fmaf(v1.x,Ax,Bx),0.f); v1.y = fmaxf(fmaf(v1.y,Ay,By),0.f);
            v2.x = fmaxf(fmaf(v2.x,Ax,Bx),0.f); v2.y = fmaxf(fmaf(v2.y,Ay,By),0.f);
            v3.x = fmaxf(fmaf(v3.x,Ax,Bx),0.f); v3.y = fmaxf(fmaf(v3.y,Ay,By),0.f);
        }
        ax += (v0.x + v1.x) + (v2.x + v3.x);
        ay += (v0.y + v1.y) + (v2.y + v3.y);
    }
    for (; e < end; e++){
        int sI = g_col[e];
        float2 v = h2[sI*32+lane];
        if (MODE){
            v.x = fmaxf(fmaf(v.x,Ax,Bx),0.f);
            v.y = fmaxf(fmaf(v.y,Ay,By),0.f);
        }
        ax += v.x; ay += v.y;
    }
    float2 o; o.x = ax; o.y = ay;
    ((float2*)g_pre)[w*32 + lane] = o;

    // pooled reduction: 8 contiguous (gid-sorted) nodes -> run-length flush per column
    __syncthreads();
    if (tid < 64){
        float acc = sPool[0][tid];
        int cur = sGid[0];
        #pragma unroll
        for (int r = 1; r < 8; r++){
            int g = sGid[r];
            if (g != cur){
                atomicAdd(&pooled[cur*64 + tid], acc);
                cur = g; acc = sPool[r][tid];
            } else {
                acc += sPool[r][tid];
            }
        }
        atomicAdd(&pooled[cur*64 + tid], acc);
    }
}

// ---------------- GEMM (100k x 64)@(64 x 64)+bias, FFMA2, fused BN-stats epilogue,
// optional fused BN+relu on the INPUT (coeffs from stats slot) ----------------
template<int APPLY>
__global__ void __launch_bounds__(256) k_gemm(const float* __restrict__ X,
                                              const float* __restrict__ W,
                                              const float* __restrict__ bias,
                                              float* __restrict__ Y,
                                              const float* __restrict__ statsIn,
                                              float* __restrict__ statsOut,
                                              const float* __restrict__ gamma,
                                              const float* __restrict__ beta)
{
    __shared__ float sXT[64][132];
    __shared__ float sW[64][64];
    __shared__ float sA[64], sB[64];
    __shared__ float sSum[64], sSsq[64];
    int tid = threadIdx.x;
    int rowBase = blockIdx.x * 128;
    if (tid < 64){ sSum[tid] = 0.f; sSsq[tid] = 0.f; }
    if (APPLY) bn_coeffs(statsIn, gamma, beta, sA, sB, tid);

    {
        const float4* W4 = (const float4*)W;
        float4* sW4 = (float4*)sW;
        #pragma unroll
        for (int i = 0; i < 4; i++) sW4[tid + i*256] = W4[tid + i*256];
    }
    __syncthreads();   // sA/sB ready

    #pragma unroll
    for (int k = 0; k < 8; k++){
        int l  = tid + k*256;
        int r  = l >> 4;
        int c4 = l & 15;
        int gr = rowBase + r;
        float4 x = make_float4(0.f,0.f,0.f,0.f);
        if (gr < Nn){
            x = ((const float4*)X)[gr*16 + c4];
            if (APPLY){
                float4 A = ((const float4*)sA)[c4];
                float4 B = ((const float4*)sB)[c4];
                x.x = fmaxf(fmaf(x.x,A.x,B.x),0.f);
                x.y = fmaxf(fmaf(x.y,A.y,B.y),0.f);
                x.z = fmaxf(fmaf(x.z,A.z,B.z),0.f);
                x.w = fmaxf(fmaf(x.w,A.w,B.w),0.f);
            }
        }
        int c = c4*4;
        sXT[c+0][r] = x.x; sXT[c+1][r] = x.y; sXT[c+2][r] = x.z; sXT[c+3][r] = x.w;
    }
    __syncthreads();

    int tr = tid >> 4;
    int tc = tid & 15;
    ull acc[4][4];
    #pragma unroll
    for (int i = 0; i < 4; i++)
        #pragma unroll
        for (int j = 0; j < 4; j++) acc[i][j] = 0ULL;

    #pragma unroll 16
    for (int k = 0; k < 64; k++){
        ulonglong2 a01 = *(const ulonglong2*)&sXT[k][tr*8];
        ulonglong2 a23 = *(const ulonglong2*)&sXT[k][tr*8 + 4];
        float4 wv = *(const float4*)&sW[k][tc*4];
        ull w0 = dup2(wv.x), w1 = dup2(wv.y), w2 = dup2(wv.z), w3 = dup2(wv.w);
        fma2(acc[0][0], a01.x, w0); fma2(acc[0][1], a01.x, w1);
        fma2(acc[0][2], a01.x, w2); fma2(acc[0][3], a01.x, w3);
        fma2(acc[1][0], a01.y, w0); fma2(acc[1][1], a01.y, w1);
        fma2(acc[1][2], a01.y, w2); fma2(acc[1][3], a01.y, w3);
        fma2(acc[2][0], a23.x, w0); fma2(acc[2][1], a23.x, w1);
        fma2(acc[2][2], a23.x, w2); fma2(acc[2][3], a23.x, w3);
        fma2(acc[3][0], a23.y, w0); fma2(acc[3][1], a23.y, w1);
        fma2(acc[3][2], a23.y, w2); fma2(acc[3][3], a23.y, w3);
    }

    float4 bi = ((const float4*)bias)[tc];
    float ls[4]  = {0.f,0.f,0.f,0.f};
    float lss[4] = {0.f,0.f,0.f,0.f};
    #pragma unroll
    for (int rp = 0; rp < 4; rp++){
        float2 c0 = u2f2(acc[rp][0]);
        float2 c1 = u2f2(acc[rp][1]);
        float2 c2 = u2f2(acc[rp][2]);
        float2 c3 = u2f2(acc[rp][3]);
        int gr = rowBase + tr*8 + rp*2;
        if (gr < Nn){
            float4 o;
            o.x = c0.x + bi.x; o.y = c1.x + bi.y; o.z = c2.x + bi.z; o.w = c3.x + bi.w;
            *(float4*)&Y[gr*64 + tc*4] = o;
            ls[0] += o.x; ls[1] += o.y; ls[2] += o.z; ls[3] += o.w;
            lss[0] += o.x*o.x; lss[1] += o.y*o.y; lss[2] += o.z*o.z; lss[3] += o.w*o.w;
        }
        if (gr + 1 < Nn){
            float4 o;
            o.x = c0.y + bi.x; o.y = c1.y + bi.y; o.z = c2.y + bi.z; o.w = c3.y + bi.w;
            *(float4*)&Y[(gr+1)*64 + tc*4] = o;
            ls[0] += o.x; ls[1] += o.y; ls[2] += o.z; ls[3] += o.w;
            lss[0] += o.x*o.x; lss[1] += o.y*o.y; lss[2] += o.z*o.z; lss[3] += o.w*o.w;
        }
    }
    #pragma unroll
    for (int c = 0; c < 4; c++){
        ls[c]  += __shfl_xor_sync(0xffffffffu, ls[c],  16);
        lss[c] += __shfl_xor_sync(0xffffffffu, lss[c], 16);
    }
    if ((tid & 31) < 16){
        #pragma unroll
        for (int c = 0; c < 4; c++){
            atomicAdd(&sSum[tc*4+c], ls[c]);
            atomicAdd(&sSsq[tc*4+c], lss[c]);
        }
    }
    __syncthreads();
    if (tid < 64){
        atomicAdd(&statsOut[tid],    sSum[tid]);
        atomicAdd(&statsOut[64+tid], sSsq[tid]);
    }
}

// ---------------- final-layer pooling (BN+relu fused), sorted run-length ----------------
__global__ void k_pool(const float* __restrict__ U, const int* __restrict__ gid,
                       float* __restrict__ pooled,
                       const float* __restrict__ statsIn,
                       const float* __restrict__ gamma,
                       const float* __restrict__ beta)
{
    __shared__ float sA[64], sB[64];
    int tid = threadIdx.x;
    bn_coeffs(statsIn, gamma, beta, sA, sB, tid);
    __syncthreads();
    int col  = tid & 63;
    int rl   = tid >> 6;
    int base = blockIdx.x * 128 + rl*32;
    float a = sA[col], b = sB[col];
    float acc = 0.f; int cur = -1;
    for (int j = 0; j < 32; j++){
        int r = base + j;
        if (r >= Nn) break;
        float x = U[r*64 + col];
        x = fmaxf(fmaf(x, a, b), 0.f);
        int g = gid[r];
        if (g != cur){
            if (cur >= 0) atomicAdd(&pooled[cur*64 + col], acc);
            cur = g; acc = x;
        } else {
            acc += x;
        }
    }
    if (cur >= 0) atomicAdd(&pooled[cur*64 + col], acc);
}

// ---------------- score = sum_i pooled_i @ Wp_i + bp_i ----------------
__global__ void k_score(const float* __restrict__ Wp, const float* __restrict__ bp,
                        float* __restrict__ out)
{
    int t = blockIdx.x*blockDim.x + threadIdx.x;
    if (t >= NG*16) return;
    int g = t >> 4, o = t & 15;
    float acc = 0.f;
    #pragma unroll
    for (int i = 0; i < NPRED; i++){
        const float* __restrict__ P  = &g_pooled[(i*NG + g)*64];
        const float* __restrict__ Wr = Wp + i*64*16 + o;
        float s = 0.f;
        #pragma unroll 16
        for (int k = 0; k < 64; k++) s = fmaf(P[k], Wr[k*16], s);
        acc += s + bp[i*16 + o];
    }
    out[t] = acc;
}

// ---------------- launch ----------------
extern "C" void kernel_launch(void* const* d_in, const int* in_sizes, int n_in,
                              void* d_out, int out_size)
{
    const float* h    = (const float*)d_in[0];
    const int*   esrc = (const int*)  d_in[1];
    const int*   edst = (const int*)  d_in[2];
    const int*   gid  = (const int*)  d_in[3];
    const float* eps  = (const float*)d_in[4];
    const float* W1   = (const float*)d_in[5];
    const float* b1   = (const float*)d_in[6];
    const float* g1   = (const float*)d_in[7];
    const float* be1  = (const float*)d_in[8];
    const float* W2   = (const float*)d_in[9];
    const float* b2   = (const float*)d_in[10];
    const float* g2   = (const float*)d_in[11];
    const float* be2  = (const float*)d_in[12];
    const float* Wp   = (const float*)d_in[13];
    const float* bp   = (const float*)d_in[14];
    float* out = (float*)d_out;

    void *p_pooled, *p_pre, *p_t, *p_u, *p_stats;
    cudaGetSymbolAddress(&p_pooled, g_pooled);
    cudaGetSymbolAddress(&p_pre,    g_pre);
    cudaGetSymbolAddress(&p_t,      g_t);
    cudaGetSymbolAddress(&p_u,      g_u);
    cudaGetSymbolAddress(&p_stats,  g_stats);
    float* stats  = (float*)p_stats;
    float* pooled = (float*)p_pooled;

    // CSR by destination (self-cleaning counters; zeroes pooled+stats too)
    k_hist<<<(Ee+255)/256, 256>>>(edst);
    int nb = (Nn + 1023)/1024;
    k_scan1<<<nb, 1024>>>();
    k_scan2<<<1, 32>>>(nb);
    k_scan3<<<nb, 1024>>>();
    k_scatter<<<(Ee+255)/256, 256>>>(esrc, edst);

    int gemmB_ = (Nn + 127)/128;
    int aggB   = Nn/8;           // 12500 full blocks (8 nodes per block)

    for (int i = 0; i < NGIN; i++){
        float* s1 = stats + (2*i)*128;
        float* s2 = stats + (2*i+1)*128;

        if (i == 0)
            k_agg<0><<<aggB, 256>>>(h, eps, 0, gid, pooled,
                                    nullptr, nullptr, nullptr);
        else
            k_agg<1><<<aggB, 256>>>((const float*)p_u, eps, i, gid,
                                    pooled + (size_t)i*NG*Dd,
                                    stats + (2*(i-1)+1)*128,
                                    g2 + (i-1)*64, be2 + (i-1)*64);

        k_gemm<0><<<gemmB_, 256>>>((const float*)p_pre, W1 + i*4096, b1 + i*64,
                                   (float*)p_t, nullptr, s1, nullptr, nullptr);
        k_gemm<1><<<gemmB_, 256>>>((const float*)p_t, W2 + i*4096, b2 + i*64,
                                   (float*)p_u, s1, s2, g1 + i*64, be1 + i*64);
    }

    k_pool<<<(Nn + 127)/128, 256>>>((const float*)p_u, gid,
                                    pooled + (size_t)NGIN*NG*Dd,
                                    stats + 7*128, g2 + 3*64, be2 + 3*64);

    k_score<<<(NG*16 + 255)/256, 256>>>(Wp, bp, out);
}